// round 1
// baseline (speedup 1.0000x reference)
#include <cuda_runtime.h>
#include <math.h>

#define NATOMS 256
#define RCR 5.2f
#define RCA 3.5f
#define PI_F 3.14159265358979323846f

__global__ void __launch_bounds__(NATOMS) aev_kernel(
    const float* __restrict__ coords,
    const float* __restrict__ charges,
    float* __restrict__ out)
{
    __shared__ float sx[NATOMS], sy[NATOMS], sz[NATOMS], sq[NATOMS];
    // angular neighbor list (dij < 3.5 A)
    __shared__ float ndx[NATOMS], ndy[NATOMS], ndz[NATOMS];
    __shared__ float nd[NATOMS], nfc[NATOMS], nq[NATOMS];
    __shared__ float acc[48];
    __shared__ int ncnt;

    const int i   = blockIdx.x;
    const int tid = threadIdx.x;

    // load all coords/charges to shared (one element per thread)
    sx[tid] = coords[tid * 3 + 0];
    sy[tid] = coords[tid * 3 + 1];
    sz[tid] = coords[tid * 3 + 2];
    sq[tid] = charges[tid];
    if (tid < 48) acc[tid] = 0.0f;
    if (tid == 0) ncnt = 0;
    __syncthreads();

    const float xi = sx[i], yi = sy[i], zi = sz[i];

    // ---------- Phase A: radial AEV + angular neighbor-list build ----------
    {
        const int j = tid;
        if (j != i) {
            const float dx = sx[j] - xi;
            const float dy = sy[j] - yi;
            const float dz = sz[j] - zi;
            const float d  = sqrtf(dx * dx + dy * dy + dz * dz);
            if (d < RCR) {
                const float fc = 0.5f * cosf(PI_F * d / RCR) + 0.5f;
                const float w  = 0.25f * fc * sq[j];
                #pragma unroll
                for (int m = 0; m < 16; m++) {
                    const float sh = 0.9f + 0.26875f * (float)m;
                    const float t  = d - sh;
                    atomicAdd(&acc[m], w * expf(-16.0f * t * t));
                }
            }
            if (d < RCA) {
                const float fca  = 0.5f * cosf(PI_F * d / RCA) + 0.5f;
                const int   slot = atomicAdd(&ncnt, 1);
                ndx[slot] = dx; ndy[slot] = dy; ndz[slot] = dz;
                nd[slot]  = d;  nfc[slot] = fca; nq[slot] = sq[j];
            }
        }
    }
    __syncthreads();

    // ---------- Phase B: angular AEV over unordered neighbor pairs ----------
    // Reference sums over ordered pairs (j != k) with unit prefactor; the
    // contribution is symmetric in (j,k), so sum unordered pairs x 2.
    const int M = ncnt;
    for (int p = tid; p < M * M; p += blockDim.x) {
        const int a = p / M;
        const int b = p % M;
        if (a >= b) continue;  // unordered pairs only

        const float da = nd[a], db = nd[b];
        const float dot = ndx[a] * ndx[b] + ndy[a] * ndy[b] + ndz[a] * ndz[b];
        const float c = 0.95f * dot / (da * db);            // cos(theta), |c| <= 0.95
        const float s = sqrtf(fmaxf(1.0f - c * c, 0.0f));   // sin(theta), theta in [0, pi]
        const float w = 2.0f * nfc[a] * nfc[b] * nq[a] * nq[b];
        const float davg = 0.5f * (da + db);

        #pragma unroll
        for (int az = 0; az < 4; az++) {
            const float sha = 0.9f + 0.65f * (float)az;
            const float t   = davg - sha;
            const float rad = w * expf(-8.0f * t * t);
            #pragma unroll
            for (int zz = 0; zz < 8; zz++) {
                // ShfZ = pi/16 + (pi/8)*zz ; cos/sin constant-fold at compile time
                const float ang = PI_F / 16.0f + (PI_F / 8.0f) * (float)zz;
                const float cz  = cosf(ang);
                const float szv = sinf(ang);
                // cos(theta - ShfZ) = c*cos(ShfZ) + sin(theta)*sin(ShfZ)  (exact)
                const float x  = 0.5f * (1.0f + c * cz + s * szv);
                // x^32 by repeated squaring
                const float x2  = x * x;
                const float x4  = x2 * x2;
                const float x8  = x4 * x4;
                const float x16 = x8 * x8;
                const float x32 = x16 * x16;
                atomicAdd(&acc[16 + az * 8 + zz], rad * x32);
            }
        }
    }
    __syncthreads();

    // ---------- write out [48] for atom i ----------
    if (tid < 48) out[i * 48 + tid] = acc[tid];
}

extern "C" void kernel_launch(void* const* d_in, const int* in_sizes, int n_in,
                              void* d_out, int out_size) {
    const float* coords  = (const float*)d_in[0];  // [256,3] fp32
    const float* charges = (const float*)d_in[1];  // [256]   fp32
    float* out = (float*)d_out;                    // [256,48] fp32
    aev_kernel<<<NATOMS, NATOMS>>>(coords, charges, out);
}

// round 2
// speedup vs baseline: 4.7292x; 4.7292x over previous
#include <cuda_runtime.h>
#include <math.h>

#define NATOMS 256
#define RCR 5.2f
#define RCA 3.5f
#define PI_F 3.14159265358979323846f
#define CAP_R 80   // radial neighbor capacity (mean ~19, 14 sigma headroom)
#define CAP_A 40   // angular neighbor capacity (mean ~5.7, 14 sigma headroom)
#define FULL 0xFFFFFFFFu

__global__ void __launch_bounds__(32) aev_kernel(
    const float* __restrict__ coords,
    const float* __restrict__ charges,
    float* __restrict__ out)
{
    // per-block (one warp) compacted neighbor lists
    __shared__ float rd[CAP_R], rq[CAP_R];                       // radial: dist, charge
    __shared__ float adx[CAP_A], ady[CAP_A], adz[CAP_A];         // angular: i->j vector
    __shared__ float ad[CAP_A], afc[CAP_A], aq[CAP_A];           // dist, cutoff, charge

    const int i    = blockIdx.x;
    const int lane = threadIdx.x;

    const float xi = __ldg(&coords[i * 3 + 0]);
    const float yi = __ldg(&coords[i * 3 + 1]);
    const float zi = __ldg(&coords[i * 3 + 2]);

    // ---------- build compact neighbor lists via ballot ----------
    int cntR = 0, cntA = 0;
    #pragma unroll
    for (int c = 0; c < NATOMS / 32; c++) {
        const int j = c * 32 + lane;
        const float dx = __ldg(&coords[j * 3 + 0]) - xi;
        const float dy = __ldg(&coords[j * 3 + 1]) - yi;
        const float dz = __ldg(&coords[j * 3 + 2]) - zi;
        const float d2 = dx * dx + dy * dy + dz * dz;
        const float d  = sqrtf(d2);
        const bool  ok = (j != i);
        const bool inR = ok && (d < RCR);
        const bool inA = ok && (d < RCA);
        const unsigned mR = __ballot_sync(FULL, inR);
        const unsigned mA = __ballot_sync(FULL, inA);
        const unsigned below = (1u << lane) - 1u;
        if (inR) {
            const int s = cntR + __popc(mR & below);
            rd[s] = d; rq[s] = __ldg(&charges[j]);
        }
        if (inA) {
            const int s = cntA + __popc(mA & below);
            adx[s] = dx; ady[s] = dy; adz[s] = dz;
            ad[s] = d;  aq[s] = __ldg(&charges[j]);
        }
        cntR += __popc(mR);
        cntA += __popc(mA);
    }
    __syncwarp();

    // ---------- radial: register accumulators, one neighbor per lane ----------
    float accR[16];
    #pragma unroll
    for (int m = 0; m < 16; m++) accR[m] = 0.0f;

    for (int t = lane; t < cntR; t += 32) {
        const float d  = rd[t];
        const float fc = 0.5f * __cosf((PI_F / RCR) * d) + 0.5f;
        const float w  = 0.25f * fc * rq[t];
        #pragma unroll
        for (int m = 0; m < 16; m++) {
            const float sh = 0.9f + 0.26875f * (float)m;
            const float u  = d - sh;
            accR[m] += w * __expf(-16.0f * u * u);
        }
    }

    // ---------- angular: precompute per-neighbor cutoff ----------
    for (int t = lane; t < cntA; t += 32)
        afc[t] = 0.5f * __cosf((PI_F / RCA) * ad[t]) + 0.5f;
    __syncwarp();

    float accA[32];
    #pragma unroll
    for (int s = 0; s < 32; s++) accA[s] = 0.0f;

    const int M = cntA;
    for (int p = lane; p < M * M; p += 32) {
        const int a = p / M;
        const int b = p % M;
        if (a >= b) continue;  // unordered pairs; reference's ordered double-count -> x2 below

        const float da = ad[a], db = ad[b];
        const float dot = adx[a] * adx[b] + ady[a] * ady[b] + adz[a] * adz[b];
        const float cth = 0.95f * dot / (da * db);              // cos(theta), |c|<=0.95
        const float sth = sqrtf(fmaxf(1.0f - cth * cth, 0.0f)); // sin(theta), theta in [0,pi]
        const float w   = 2.0f * afc[a] * afc[b] * aq[a] * aq[b];
        const float davg = 0.5f * (da + db);

        #pragma unroll
        for (int az = 0; az < 4; az++) {
            const float sha = 0.9f + 0.65f * (float)az;
            const float u   = davg - sha;
            const float rad = w * __expf(-8.0f * u * u);
            #pragma unroll
            for (int zz = 0; zz < 8; zz++) {
                const float ang = PI_F / 16.0f + (PI_F / 8.0f) * (float)zz;
                const float cz  = cosf(ang);   // compile-time constants
                const float sz  = sinf(ang);
                // cos(theta - ShfZ) = cth*cos(ShfZ) + sin(theta)*sin(ShfZ)  (exact)
                const float x   = 0.5f * (1.0f + cth * cz + sth * sz);
                const float x2  = x * x;
                const float x4  = x2 * x2;
                const float x8  = x4 * x4;
                const float x16 = x8 * x8;
                accA[az * 8 + zz] += rad * (x16 * x16);
            }
        }
    }

    // ---------- warp butterfly reductions ----------
    #pragma unroll
    for (int m = 0; m < 16; m++) {
        float v = accR[m];
        #pragma unroll
        for (int off = 16; off > 0; off >>= 1) v += __shfl_xor_sync(FULL, v, off);
        accR[m] = v;
    }
    #pragma unroll
    for (int s = 0; s < 32; s++) {
        float v = accA[s];
        #pragma unroll
        for (int off = 16; off > 0; off >>= 1) v += __shfl_xor_sync(FULL, v, off);
        accA[s] = v;
    }

    // ---------- lane 0 writes [48] for atom i ----------
    if (lane == 0) {
        #pragma unroll
        for (int m = 0; m < 16; m++) out[i * 48 + m] = accR[m];
        #pragma unroll
        for (int s = 0; s < 32; s++) out[i * 48 + 16 + s] = accA[s];
    }
}

extern "C" void kernel_launch(void* const* d_in, const int* in_sizes, int n_in,
                              void* d_out, int out_size) {
    const float* coords  = (const float*)d_in[0];  // [256,3] fp32
    const float* charges = (const float*)d_in[1];  // [256]   fp32
    float* out = (float*)d_out;                    // [256,48] fp32
    aev_kernel<<<NATOMS, 32>>>(coords, charges, out);
}